// round 13
// baseline (speedup 1.0000x reference)
#include <cuda_runtime.h>
#include <cstdint>
#include <cstddef>

#define SEQ   2048
#define BATCH 128
#define HID   256
#define CSIZE 4         // CTAs per cluster
#define NCTA  256       // 64 clusters * 4 CTAs
#define HSTRIDE 132     // 128 cols + 4 pad floats (bank-shift between halves)

// ---------------- f32x2 packed helpers (sm_103a) ----------------
__device__ __forceinline__ unsigned long long pk2(float x, float y){
    unsigned long long r; asm("mov.b64 %0, {%1,%2};" : "=l"(r) : "f"(x), "f"(y)); return r;
}
__device__ __forceinline__ void upk2(unsigned long long v, float& x, float& y){
    asm("mov.b64 {%0,%1}, %2;" : "=f"(x), "=f"(y) : "l"(v));
}
__device__ __forceinline__ unsigned long long ffma2(unsigned long long a,
                                                    unsigned long long b,
                                                    unsigned long long c){
    unsigned long long d;
    asm("fma.rn.f32x2 %0, %1, %2, %3;" : "=l"(d) : "l"(a), "l"(b), "l"(c));
    return d;
}

// ---------------- smem / cluster helpers (proven R5/R9) ----------------
__device__ __forceinline__ unsigned smem_u32(const void* p){
    return (unsigned)__cvta_generic_to_shared(p);
}
__device__ __forceinline__ unsigned mapa_u32(unsigned laddr, unsigned peer){
    unsigned r;
    asm("mapa.shared::cluster.u32 %0, %1, %2;" : "=r"(r) : "r"(laddr), "r"(peer));
    return r;
}
__device__ __forceinline__ void mbar_init(unsigned a, unsigned cnt){
    asm volatile("mbarrier.init.shared.b64 [%0], %1;" :: "r"(a), "r"(cnt) : "memory");
}
__device__ __forceinline__ void mbar_inval(unsigned a){
    asm volatile("mbarrier.inval.shared.b64 [%0];" :: "r"(a) : "memory");
}
__device__ __forceinline__ void st_remote_f(unsigned raddr, float v){
    asm volatile("st.shared::cluster.b32 [%0], %1;" :: "r"(raddr), "f"(v) : "memory");
}
__device__ __forceinline__ void arrive_remote(unsigned raddr){
    asm volatile("mbarrier.arrive.release.cluster.shared::cluster.b64 _, [%0];"
                 :: "r"(raddr) : "memory");
}
__device__ __forceinline__ void mbar_wait_acq_cluster(unsigned a, unsigned parity){
    asm volatile(
        "{\n\t.reg .pred P;\n\t"
        "WL_%=:\n\t"
        "mbarrier.try_wait.parity.acquire.cluster.shared::cta.b64 P, [%0], %1, 0x989680;\n\t"
        "@!P bra WL_%=;\n\t"
        "}"
        :: "r"(a), "r"(parity) : "memory");
}
__device__ __forceinline__ void cluster_sync_hw(){
    asm volatile("barrier.cluster.arrive.aligned;" ::: "memory");
    asm volatile("barrier.cluster.wait.aligned;"   ::: "memory");
}
__device__ __forceinline__ unsigned cta_rank(){
    unsigned r; asm("mov.u32 %0, %%cluster_ctarank;" : "=r"(r)); return r;
}
__device__ __forceinline__ float sigmoidf(float x){
    return __fdividef(1.f, 1.f + __expf(-x));
}

// =====================================================================
// Persistent RNN: 64 clusters x 4 CTAs (128 thr), 2 batches/cluster,
// 2 CTAs co-resident per SM (occupancy-2 -> stall overlap between
// independent clusters). CTA r owns rows [r*64, r*64+64) x all 256 cols.
// Thread (w,l): row iloc = w*16+(l&15), col-half jh = l>>4 (128 cols,
// 128 weight regs). Per step: FFMA both batches over my col-half ->
// shfl_xor(16) full-row sums -> thread finalizes (row iglob, batch jh):
// sigmoid, STG h, STS local activation, st.shared::cluster to 3 peers,
// elected release-arrives (count-12 mbar), B2, bottom wait on nxt.
// =====================================================================
__global__ void __cluster_dims__(CSIZE,1,1) __launch_bounds__(128,2)
rnn_kernel(const float* __restrict__ x,      // (SEQ, BATCH)
           const float* __restrict__ h0,     // (BATCH, HID)
           const float* __restrict__ W_ih,   // (HID, 1)
           const float* __restrict__ W_hh,   // (HID, HID)
           const float* __restrict__ W_hhb,  // (HID, HID)
           const float* __restrict__ b_h,    // (HID,)
           const void*  __restrict__ ctxp,   // scalar
           float* __restrict__ outbuf)       // (BATCH, SEQ, HID)
{
    // sa[buf][batch][half][HSTRIDE]; halves padded to avoid bank overlap
    __shared__ __align__(16) float sa[2][2][2][HSTRIDE];   // ~4.2 KB
    __shared__ float sx[SEQ * 2];                          // 16 KB
    __shared__ __align__(8) unsigned long long mb[2];      // per-buffer

    const int t = (int)threadIdx.x;
    const int w = t >> 5, l = t & 31;
    const unsigned rank = cta_rank();          // 0..3
    const int cid   = (int)blockIdx.x >> 2;
    const int b0    = cid * 2;
    const int iloc  = w * 16 + (l & 15);       // 0..63
    const int iglob = (int)rank * 64 + iloc;   // my output row
    const int jh    = l >> 4;                  // col half (FFMA) / batch (epilogue)

    float ctx;
    {
        int   iv = *(const int*)ctxp;
        float fv = *(const float*)ctxp;
        ctx = (iv >= -1000000 && iv <= 1000000) ? (float)iv : fv;
    }

    // ---- weights: row iglob, cols [jh*128, jh*128+128), f32x2-packed ----
    unsigned long long wreg[64];
    {
        const float4* wh = reinterpret_cast<const float4*>(W_hh  + (size_t)iglob * HID + jh * 128);
        const float4* wb = reinterpret_cast<const float4*>(W_hhb + (size_t)iglob * HID + jh * 128);
        #pragma unroll
        for (int m = 0; m < 32; ++m){
            float4 a4 = wh[m], c4 = wb[m];
            wreg[2*m]   = pk2(fmaf(ctx, c4.x, a4.x), fmaf(ctx, c4.y, a4.y));
            wreg[2*m+1] = pk2(fmaf(ctx, c4.z, a4.z), fmaf(ctx, c4.w, a4.w));
        }
    }
    const float win_r = W_ih[iglob];
    const float bh_r  = b_h[iglob];

    // ---- preload x columns for b0/b1 ----
    for (int idx = t; idx < SEQ * 2; idx += 128){
        sx[idx] = x[(size_t)(idx >> 1) * BATCH + b0 + (idx & 1)];
    }
    // ---- init sa[0] from h0 (both batches, all cols) ----
    for (int idx = t; idx < 512; idx += 128){
        int bb = idx >> 8, c = idx & 255;
        sa[0][bb][c >> 7][c & 127] = fmaf(2.f, h0[(size_t)(b0 + bb) * HID + c], -1.f);
    }
    const unsigned mb_l = smem_u32(&mb[0]);
    if (t == 0){
        mbar_init(mb_l + 0u, 12);   // 3 peers x 4 warps
        mbar_init(mb_l + 8u, 12);
    }
    __syncthreads();
    cluster_sync_hw();   // mbars + sa[0] visible cluster-wide

    // ---- peer addressing (3 peers) ----
    const unsigned sa_u32 = smem_u32(&sa[0][0][0][0]);
    unsigned sa_r[3], mb_r[3];
    {
        int pi = 0;
        #pragma unroll
        for (int p = 0; p < CSIZE; ++p){
            if ((unsigned)p != rank){
                sa_r[pi] = mapa_u32(sa_u32, (unsigned)p);
                mb_r[pi] = mapa_u32(mb_l,  (unsigned)p);
                ++pi;
            }
        }
    }

    float* outp = outbuf + (size_t)(b0 + jh) * SEQ * HID + iglob;
    // activation slot for (batch jh, col iglob)
    const unsigned aoff = (unsigned)((jh * 2 + (iglob >> 7)) * HSTRIDE + (iglob & 127)) * 4u;
    const unsigned abuf = (unsigned)(2 * 2 * HSTRIDE) * 4u;   // bytes per buffer

    int ph[2] = {0, 0};
    int cur = 0;

    for (int step = 0; step < SEQ; ++step){
        const int nxt = cur ^ 1;

        // ---- FFMA over my col-half, both batches (4 chains, 32 deep) ----
        const ulonglong2* a0p = reinterpret_cast<const ulonglong2*>(&sa[cur][0][jh][0]);
        const ulonglong2* a1p = reinterpret_cast<const ulonglong2*>(&sa[cur][1][jh][0]);
        unsigned long long acc00 = 0ull, acc01 = 0ull, acc10 = 0ull, acc11 = 0ull;
        #pragma unroll
        for (int m = 0; m < 32; ++m){
            ulonglong2 A0 = a0p[m];
            ulonglong2 A1 = a1p[m];
            acc00 = ffma2(wreg[2*m],   A0.x, acc00);
            acc01 = ffma2(wreg[2*m+1], A0.y, acc01);
            acc10 = ffma2(wreg[2*m],   A1.x, acc10);
            acc11 = ffma2(wreg[2*m+1], A1.y, acc11);
        }
        float s0a, s0b, s0c, s0d, s1a, s1b, s1c, s1d;
        upk2(acc00, s0a, s0b); upk2(acc01, s0c, s0d);
        upk2(acc10, s1a, s1b); upk2(acc11, s1c, s1d);
        float p0 = (s0a + s0b) + (s0c + s0d);     // batch-0 partial (my half)
        float p1 = (s1a + s1b) + (s1c + s1d);     // batch-1 partial
        float q0 = __shfl_xor_sync(0xFFFFFFFFu, p0, 16);   // pair lane: other half
        float q1 = __shfl_xor_sync(0xFFFFFFFFu, p1, 16);
        float mysum = jh ? (p1 + q1) : (p0 + q0);          // full row, my batch

        // ---- finalize (row iglob, batch b0+jh) ----
        float pre = mysum + fmaf(sx[2*step + jh], win_r, bh_r);
        float hv  = sigmoidf(pre);
        outp[(size_t)step * HID] = hv;
        float av = fmaf(2.f, hv, -1.f);
        const unsigned dst = (unsigned)nxt * abuf + aoff;
        *reinterpret_cast<float*>(reinterpret_cast<char*>(&sa[0][0][0][0]) + dst) = av;
        st_remote_f(sa_r[0] + dst, av);
        st_remote_f(sa_r[1] + dst, av);
        st_remote_f(sa_r[2] + dst, av);
        __syncwarp();
        if (l == 0){
            const unsigned mo = (unsigned)nxt * 8u;
            arrive_remote(mb_r[0] + mo);
            arrive_remote(mb_r[1] + mo);
            arrive_remote(mb_r[2] + mo);
        }
        __syncthreads();   // local rows of sa[nxt] visible CTA-wide

        // ---- bottom wait: 3 peers' row-chunks for buffer nxt ----
        mbar_wait_acq_cluster(mb_l + (unsigned)nxt * 8u, (unsigned)ph[nxt]);
        ph[nxt] ^= 1;

        cur = nxt;
    }

    cluster_sync_hw();   // no CTA exits while peers may still write our smem
    if (t == 0){ mbar_inval(mb_l + 0u); mbar_inval(mb_l + 8u); }
}

// =====================================================================
// y[b,t] = out[b,t,:] . W[0,:] + b[0]   (one warp per (b,t) row)
// =====================================================================
__global__ void __launch_bounds__(256)
y_kernel(const float* __restrict__ outbuf,
         const float* __restrict__ W,
         const float* __restrict__ bb,
         float* __restrict__ y)
{
    int row  = (int)blockIdx.x * 8 + ((int)threadIdx.x >> 5);
    int lane = (int)threadIdx.x & 31;
    const float4* p  = reinterpret_cast<const float4*>(outbuf + (size_t)row * HID);
    const float4* wp = reinterpret_cast<const float4*>(W);
    float4 a = p[lane*2],  b4 = p[lane*2 + 1];
    float4 u = wp[lane*2], v  = wp[lane*2 + 1];
    float s = a.x*u.x + a.y*u.y + a.z*u.z + a.w*u.w
            + b4.x*v.x + b4.y*v.y + b4.z*v.z + b4.w*v.w;
    #pragma unroll
    for (int off = 16; off; off >>= 1) s += __shfl_xor_sync(0xFFFFFFFFu, s, off);
    if (lane == 0) y[row] = s + bb[0];
}

extern "C" void kernel_launch(void* const* d_in, const int* in_sizes, int n_in,
                              void* d_out, int out_size)
{
    const float* x     = (const float*)d_in[0];
    const float* h0    = (const float*)d_in[1];
    const float* W_ih  = (const float*)d_in[2];
    const float* W_hh  = (const float*)d_in[3];
    const float* W_hhb = (const float*)d_in[4];
    const float* b_h   = (const float*)d_in[5];
    const float* W     = (const float*)d_in[6];
    const float* b     = (const float*)d_in[7];
    const void*  ctx   = d_in[8];

    float* y      = (float*)d_out;                 // (BATCH, SEQ)
    float* outbuf = y + (size_t)BATCH * SEQ;       // (BATCH, SEQ, HID)

    rnn_kernel<<<NCTA, 128>>>(x, h0, W_ih, W_hh, W_hhb, b_h, ctx, outbuf);
    y_kernel<<<(BATCH * SEQ) / 8, 256>>>(outbuf, W, b, y);
}

// round 15
// speedup vs baseline: 1.5365x; 1.5365x over previous
#include <cuda_runtime.h>
#include <cstdint>
#include <cstddef>

#define SEQ   2048
#define BATCH 128
#define HID   256
#define NCTA  128       // 64 clusters * 2 CTAs
#define HSTRIDE 132     // 128 cols + 4 pad floats (banks of the two halves disjoint)

// ---------------- f32x2 packed helpers (sm_103a) ----------------
__device__ __forceinline__ unsigned long long pk2(float x, float y){
    unsigned long long r; asm("mov.b64 %0, {%1,%2};" : "=l"(r) : "f"(x), "f"(y)); return r;
}
__device__ __forceinline__ void upk2(unsigned long long v, float& x, float& y){
    asm("mov.b64 {%0,%1}, %2;" : "=f"(x), "=f"(y) : "l"(v));
}
__device__ __forceinline__ unsigned long long ffma2(unsigned long long a,
                                                    unsigned long long b,
                                                    unsigned long long c){
    unsigned long long d;
    asm("fma.rn.f32x2 %0, %1, %2, %3;" : "=l"(d) : "l"(a), "l"(b), "l"(c));
    return d;
}

// ---------------- smem / cluster helpers (proven R5/R9) ----------------
__device__ __forceinline__ unsigned smem_u32(const void* p){
    return (unsigned)__cvta_generic_to_shared(p);
}
__device__ __forceinline__ unsigned mapa_u32(unsigned laddr, unsigned peer){
    unsigned r;
    asm("mapa.shared::cluster.u32 %0, %1, %2;" : "=r"(r) : "r"(laddr), "r"(peer));
    return r;
}
__device__ __forceinline__ void mbar_init(unsigned a, unsigned cnt){
    asm volatile("mbarrier.init.shared.b64 [%0], %1;" :: "r"(a), "r"(cnt) : "memory");
}
__device__ __forceinline__ void mbar_inval(unsigned a){
    asm volatile("mbarrier.inval.shared.b64 [%0];" :: "r"(a) : "memory");
}
__device__ __forceinline__ void st_remote_f(unsigned raddr, float v){
    asm volatile("st.shared::cluster.b32 [%0], %1;" :: "r"(raddr), "f"(v) : "memory");
}
__device__ __forceinline__ void arrive_remote(unsigned raddr){
    asm volatile("mbarrier.arrive.release.cluster.shared::cluster.b64 _, [%0];"
                 :: "r"(raddr) : "memory");
}
__device__ __forceinline__ void mbar_wait_acq_cluster(unsigned a, unsigned parity){
    asm volatile(
        "{\n\t.reg .pred P;\n\t"
        "WL_%=:\n\t"
        "mbarrier.try_wait.parity.acquire.cluster.shared::cta.b64 P, [%0], %1, 0x989680;\n\t"
        "@!P bra WL_%=;\n\t"
        "}"
        :: "r"(a), "r"(parity) : "memory");
}
__device__ __forceinline__ void cluster_sync_hw(){
    asm volatile("barrier.cluster.arrive.aligned;" ::: "memory");
    asm volatile("barrier.cluster.wait.aligned;"   ::: "memory");
}
__device__ __forceinline__ unsigned cta_rank(){
    unsigned r; asm("mov.u32 %0, %%cluster_ctarank;" : "=r"(r)); return r;
}
__device__ __forceinline__ float sigmoidf(float x){
    return __fdividef(1.f, 1.f + __expf(-x));
}

// =====================================================================
// Persistent RNN: 64 clusters x 2 CTAs (256 thr), 2 batches/cluster.
// CTA r owns rows [r*128, r*128+128). Thread (w,l):
//   row iloc = w*16 + (l&15)  (16 rows per warp)
//   col-half ch = l>>4        (lane pair l^16 covers the other half)
// Per step:
//   FFMA both batches over my col-half (128 FFMA2, reg weights)
//   shfl_xor(16) -> full-row sums in-warp      [kills B1 + part[] smem]
//   finalize (row iglob, batch ch): sigmoid, STG h, STS local activation
//   __syncthreads (B2: local half of sa[nxt] visible; drains LOCAL STS only)
//   st.shared::cluster to peer + elected release-arrive  [after B2 -> no
//   DSMEM drain on the barrier path]
//   bottom wait on mbar[nxt] (peer half of sa[nxt] visible)
// One BAR + one TRYWAIT per step.
// =====================================================================
__global__ void __cluster_dims__(2,1,1) __launch_bounds__(256,1)
rnn_kernel(const float* __restrict__ x,      // (SEQ, BATCH)
           const float* __restrict__ h0,     // (BATCH, HID)
           const float* __restrict__ W_ih,   // (HID, 1)
           const float* __restrict__ W_hh,   // (HID, HID)
           const float* __restrict__ W_hhb,  // (HID, HID)
           const float* __restrict__ b_h,    // (HID,)
           const void*  __restrict__ ctxp,   // scalar
           float* __restrict__ outbuf)       // (BATCH, SEQ, HID)
{
    // sa[buf][batch][half][HSTRIDE]  (halves bank-shifted by 4 banks)
    __shared__ __align__(16) float sa[2][2][2][HSTRIDE];   // ~8.4 KB
    __shared__ float sx[SEQ * 2];                          // 16 KB
    __shared__ __align__(8) unsigned long long mb[2];      // per-buffer

    const int t = (int)threadIdx.x;
    const int w = t >> 5, l = t & 31;
    const unsigned rank = cta_rank();
    const unsigned peer = rank ^ 1u;
    const int cid   = (int)blockIdx.x >> 1;
    const int b0    = cid * 2;
    const int iloc  = w * 16 + (l & 15);        // 0..127
    const int iglob = ((int)rank << 7) + iloc;  // my output row
    const int ch    = l >> 4;                   // col half (FFMA) / batch (epilogue)

    float ctx;
    {
        int   iv = *(const int*)ctxp;
        float fv = *(const float*)ctxp;
        ctx = (iv >= -1000000 && iv <= 1000000) ? (float)iv : fv;
    }

    // ---- weights: row iglob, cols [ch*128, ch*128+128), f32x2-packed ----
    unsigned long long wreg[64];
    {
        const float4* wh = reinterpret_cast<const float4*>(W_hh  + (size_t)iglob * HID + ch * 128);
        const float4* wb = reinterpret_cast<const float4*>(W_hhb + (size_t)iglob * HID + ch * 128);
        #pragma unroll
        for (int m = 0; m < 32; ++m){
            float4 a4 = wh[m], c4 = wb[m];
            wreg[2*m]   = pk2(fmaf(ctx, c4.x, a4.x), fmaf(ctx, c4.y, a4.y));
            wreg[2*m+1] = pk2(fmaf(ctx, c4.z, a4.z), fmaf(ctx, c4.w, a4.w));
        }
    }
    const float win_r = W_ih[iglob];
    const float bh_r  = b_h[iglob];

    // ---- preload x columns for b0/b1 ----
    for (int idx = t; idx < SEQ * 2; idx += 256){
        sx[idx] = x[(size_t)(idx >> 1) * BATCH + b0 + (idx & 1)];
    }
    // ---- init sa[0] fully from h0 (both batches, both halves; no exchange) ----
    for (int idx = t; idx < 512; idx += 256){
        int bb = idx >> 8, c = idx & 255;
        sa[0][bb][c >> 7][c & 127] = fmaf(2.f, h0[(size_t)(b0 + bb) * HID + c], -1.f);
    }
    const unsigned mb_l = smem_u32(&mb[0]);
    if (t == 0){
        mbar_init(mb_l + 0u, 8);   // 8 peer warps, one elected arrive each
        mbar_init(mb_l + 8u, 8);
    }
    __syncthreads();
    cluster_sync_hw();   // mbars + sa[0] visible cluster-wide

    const unsigned sa_u32 = smem_u32(&sa[0][0][0][0]);
    const unsigned sa_r   = mapa_u32(sa_u32, peer);
    const unsigned mb_r   = mapa_u32(mb_l, peer);

    float* outp = outbuf + (size_t)(b0 + ch) * SEQ * HID + iglob;
    // my activation slot: (batch ch, half rank, offset iloc)
    const unsigned aoff = (unsigned)((ch * 2 + (int)rank) * HSTRIDE + iloc) * 4u;
    const unsigned abuf = (unsigned)(2 * 2 * HSTRIDE) * 4u;   // bytes per buffer

    int ph[2] = {0, 0};
    int cur = 0;

    for (int step = 0; step < SEQ; ++step){
        const int nxt = cur ^ 1;

        // ---- FFMA over my col-half, both batches ----
        const ulonglong2* a0p = reinterpret_cast<const ulonglong2*>(&sa[cur][0][ch][0]);
        const ulonglong2* a1p = reinterpret_cast<const ulonglong2*>(&sa[cur][1][ch][0]);
        unsigned long long acc00 = 0ull, acc01 = 0ull, acc10 = 0ull, acc11 = 0ull;
        #pragma unroll
        for (int m = 0; m < 32; ++m){
            ulonglong2 A0 = a0p[m];
            ulonglong2 A1 = a1p[m];
            acc00 = ffma2(wreg[2*m],   A0.x, acc00);
            acc01 = ffma2(wreg[2*m+1], A0.y, acc01);
            acc10 = ffma2(wreg[2*m],   A1.x, acc10);
            acc11 = ffma2(wreg[2*m+1], A1.y, acc11);
        }
        float s0a, s0b, s0c, s0d, s1a, s1b, s1c, s1d;
        upk2(acc00, s0a, s0b); upk2(acc01, s0c, s0d);
        upk2(acc10, s1a, s1b); upk2(acc11, s1c, s1d);
        float p0 = (s0a + s0b) + (s0c + s0d);              // batch-0, my half
        float p1 = (s1a + s1b) + (s1c + s1d);              // batch-1, my half
        float q0 = __shfl_xor_sync(0xFFFFFFFFu, p0, 16);   // pair lane: other half
        float q1 = __shfl_xor_sync(0xFFFFFFFFu, p1, 16);
        float mysum = ch ? (p1 + q1) : (p0 + q0);          // full row, batch ch

        // ---- finalize (row iglob, batch b0+ch) ----
        float pre = mysum + fmaf(sx[2*step + ch], win_r, bh_r);
        float hv  = sigmoidf(pre);
        outp[(size_t)step * HID] = hv;
        float av = fmaf(2.f, hv, -1.f);
        const unsigned dst = (unsigned)nxt * abuf + aoff;
        *reinterpret_cast<float*>(reinterpret_cast<char*>(&sa[0][0][0][0]) + dst) = av;

        __syncthreads();   // B2: done reading sa[cur]; local half of sa[nxt] visible

        // ---- ship to peer AFTER the barrier (no DSMEM drain on BAR path) ----
        st_remote_f(sa_r + dst, av);
        __syncwarp();
        if (l == 0) arrive_remote(mb_r + (unsigned)nxt * 8u);

        // ---- bottom wait: peer half of sa[nxt] ----
        mbar_wait_acq_cluster(mb_l + (unsigned)nxt * 8u, (unsigned)ph[nxt]);
        ph[nxt] ^= 1;

        cur = nxt;
    }

    cluster_sync_hw();   // no CTA exits while peer may still write our smem
    if (t == 0){ mbar_inval(mb_l + 0u); mbar_inval(mb_l + 8u); }
}

// =====================================================================
// y[b,t] = out[b,t,:] . W[0,:] + b[0]   (one warp per (b,t) row)
// =====================================================================
__global__ void __launch_bounds__(256)
y_kernel(const float* __restrict__ outbuf,
         const float* __restrict__ W,
         const float* __restrict__ bb,
         float* __restrict__ y)
{
    int row  = (int)blockIdx.x * 8 + ((int)threadIdx.x >> 5);
    int lane = (int)threadIdx.x & 31;
    const float4* p  = reinterpret_cast<const float4*>(outbuf + (size_t)row * HID);
    const float4* wp = reinterpret_cast<const float4*>(W);
    float4 a = p[lane*2],  b4 = p[lane*2 + 1];
    float4 u = wp[lane*2], v  = wp[lane*2 + 1];
    float s = a.x*u.x + a.y*u.y + a.z*u.z + a.w*u.w
            + b4.x*v.x + b4.y*v.y + b4.z*v.z + b4.w*v.w;
    #pragma unroll
    for (int off = 16; off; off >>= 1) s += __shfl_xor_sync(0xFFFFFFFFu, s, off);
    if (lane == 0) y[row] = s + bb[0];
}

extern "C" void kernel_launch(void* const* d_in, const int* in_sizes, int n_in,
                              void* d_out, int out_size)
{
    const float* x     = (const float*)d_in[0];
    const float* h0    = (const float*)d_in[1];
    const float* W_ih  = (const float*)d_in[2];
    const float* W_hh  = (const float*)d_in[3];
    const float* W_hhb = (const float*)d_in[4];
    const float* b_h   = (const float*)d_in[5];
    const float* W     = (const float*)d_in[6];
    const float* b     = (const float*)d_in[7];
    const void*  ctx   = d_in[8];

    float* y      = (float*)d_out;                 // (BATCH, SEQ)
    float* outbuf = y + (size_t)BATCH * SEQ;       // (BATCH, SEQ, HID)

    rnn_kernel<<<NCTA, 256>>>(x, h0, W_ih, W_hh, W_hhb, b_h, ctx, outbuf);
    y_kernel<<<(BATCH * SEQ) / 8, 256>>>(outbuf, W, b, y);
}